// round 1
// baseline (speedup 1.0000x reference)
#include <cuda_runtime.h>

// y[b,c,h,w] = coef[c] * g[b,c,h,w]
// g: (32, 512, 64, 64) fp32. Inner plane H*W = 4096 floats = 1024 float4.
// One block (256 threads x 4 float4/thread) covers exactly one channel plane,
// so coef index per block = blockIdx.x & 511 (planes ordered b-major, c-minor).

__global__ void __launch_bounds__(256, 8) scale_kernel(
    const float4* __restrict__ g,
    const float* __restrict__ coef,
    float4* __restrict__ out)
{
    // Each block handles 1024 consecutive float4s = one (b, c) plane.
    const unsigned plane = blockIdx.x;          // 0 .. 32*512-1
    const unsigned c = plane & 511u;            // channel index
    const float s = __ldg(coef + c);            // broadcast, L1-cached

    const unsigned base = plane * 1024u + threadIdx.x;

    // 4 independent front-batched loads (stride 256 float4s = 4 KiB) -> MLP=4
    float4 a0 = g[base];
    float4 a1 = g[base + 256u];
    float4 a2 = g[base + 512u];
    float4 a3 = g[base + 768u];

    a0.x *= s; a0.y *= s; a0.z *= s; a0.w *= s;
    a1.x *= s; a1.y *= s; a1.z *= s; a1.w *= s;
    a2.x *= s; a2.y *= s; a2.z *= s; a2.w *= s;
    a3.x *= s; a3.y *= s; a3.z *= s; a3.w *= s;

    out[base]        = a0;
    out[base + 256u] = a1;
    out[base + 512u] = a2;
    out[base + 768u] = a3;
}

extern "C" void kernel_launch(void* const* d_in, const int* in_sizes, int n_in,
                              void* d_out, int out_size)
{
    const float4* g    = (const float4*)d_in[0];
    const float*  coef = (const float*)d_in[1];
    float4*       out  = (float4*)d_out;

    // 32 * 512 planes, one block each.
    scale_kernel<<<32 * 512, 256>>>(g, coef, out);
}